// round 17
// baseline (speedup 1.0000x reference)
#include <cuda_runtime.h>
#include <math.h>

#define MAXB 4096
#define NCTR 64
#define CTR_STRIDE 32              // uints; counters 128 B apart (distinct L2 lines)
__device__ float    g_seg_bce[MAXB];            // zero-init; spinner re-zeroes
__device__ float    g_seg_cnt[MAXB];
__device__ unsigned g_cnt[NCTR * CTR_STRIDE];   // zero-init; spinner re-zeroes
__device__ float    g_sat;                      // zero-init; spinner re-zeroes

__device__ __forceinline__ float bce_fast(float p, float t) {
    float lp = fmaxf(__logf(p),        -100.0f);   // __logf(0) = -inf -> -100
    float lq = fmaxf(__logf(1.0f - p), -100.0f);
    return -(t * lp + (1.0f - t) * lq);
}

__device__ __forceinline__ unsigned ld_acq(const unsigned* a) {
    unsigned v;
    asm volatile("ld.acquire.gpu.global.u32 %0, [%1];" : "=r"(v) : "l"(a) : "memory");
    return v;
}

__global__ void __launch_bounds__(256) fused_kernel(
        const float* __restrict__ pred,
        const float* __restrict__ tgt,
        const int*   __restrict__ batch,
        const int*   __restrict__ mask,
        const float* __restrict__ sat_p,
        const float* __restrict__ sat_t,
        float*       __restrict__ out,
        int n4, int N, int B, float l1)
{
    const unsigned FULL = 0xffffffffu;
    const float4* pred4 = (const float4*)pred;
    const float4* tgt4  = (const float4*)tgt;
    const int4*   mask4 = (const int4*)mask;

    bool is_spinner = (blockIdx.x == gridDim.x - 1);

    // block 0: saturation BCE into g_sat (REDG), plus scalar tail (N % 4).
    // Both are ordered before block 0's ticket RED by the barrier below.
    if (blockIdx.x == 0) {
        float s = 0.0f;
        for (int j = threadIdx.x; j < B; j += blockDim.x)
            s += bce_fast(sat_p[j], sat_t[j]);
        s *= l1 / (float)B;
        #pragma unroll
        for (int o = 16; o; o >>= 1) s += __shfl_down_sync(FULL, s, o);
        if ((threadIdx.x & 31) == 0) atomicAdd(&g_sat, s);   // RED (result unused)

        int tail = N - (n4 << 2);
        if ((int)threadIdx.x < tail) {
            int j = (n4 << 2) + threadIdx.x;
            float mm = (float)mask[j];
            atomicAdd(&g_seg_bce[batch[j]], bce_fast(pred[j] * mm, tgt[j]));
            atomicAdd(&g_seg_cnt[batch[j]], mm);
        }
    }

    // ---- node phase: proven R13 body (blockDim 256, endpoint probe) ----
    int i = blockIdx.x * blockDim.x + threadIdx.x;
    if (i < n4) {
        int lane = threadIdx.x & 31;
        unsigned act = __activemask();

        float4 p4 = __ldcs(&pred4[i]);
        float4 t4 = __ldcs(&tgt4[i]);
        int4   k4 = __ldcs(&mask4[i]);

        int   im = (k4.x + k4.y) + (k4.z + k4.w);
        float m0 = (float)k4.x, m1 = (float)k4.y, m2 = (float)k4.z, m3 = (float)k4.w;
        float b0 = bce_fast(p4.x * m0, t4.x);
        float b1 = bce_fast(p4.y * m1, t4.y);
        float b2 = bce_fast(p4.z * m2, t4.z);
        float b3 = bce_fast(p4.w * m3, t4.w);

        bool done = false;
        if (act == FULL) {
            int base_node = (i - lane) << 2;
            int sv = 0;
            if (lane == 0)  sv = __ldcs(&batch[base_node]);
            if (lane == 31) sv = __ldcs(&batch[base_node + 127]);
            int wlo = __shfl_sync(FULL, sv, 0);
            int whi = __shfl_sync(FULL, sv, 31);
            if (wlo == whi) {
                float b = (b0 + b1) + (b2 + b3);
                int  ws = __reduce_add_sync(FULL, im);
                #pragma unroll
                for (int o = 16; o; o >>= 1)
                    b += __shfl_down_sync(FULL, b, o);
                if (lane == 0) {
                    atomicAdd(&g_seg_bce[wlo], b);
                    atomicAdd(&g_seg_cnt[wlo], (float)ws);
                }
                done = true;
            }
        }
        if (!done) {
            const int4* batch4 = (const int4*)batch;
            int4 s4 = __ldcs(&batch4[i]);
            if (s4.x == s4.w) {
                atomicAdd(&g_seg_bce[s4.x], (b0 + b1) + (b2 + b3));
                atomicAdd(&g_seg_cnt[s4.x], (float)im);
            } else {
                atomicAdd(&g_seg_bce[s4.x], b0); atomicAdd(&g_seg_cnt[s4.x], m0);
                atomicAdd(&g_seg_bce[s4.y], b1); atomicAdd(&g_seg_cnt[s4.y], m1);
                atomicAdd(&g_seg_bce[s4.z], b2); atomicAdd(&g_seg_cnt[s4.z], m2);
                atomicAdd(&g_seg_bce[s4.w], b3); atomicAdd(&g_seg_cnt[s4.w], m3);
            }
        }
    }

    // ---- worker CTAs: one fire-and-forget release-RED, then retire ----
    __syncthreads();   // all this CTA's REDs are program-order before the ticket
    if (!is_spinner) {
        if (threadIdx.x == 0) {
            unsigned* c = &g_cnt[(blockIdx.x & (NCTR - 1)) * CTR_STRIDE];
            asm volatile("red.release.gpu.global.add.u32 [%0], %1;"
                         :: "l"(c), "r"(1u) : "memory");   // no return: no tail stall
        }
        return;
    }

    // ---- spinner CTA: poll 64 counters, then run the epilogue ----
    __shared__ int      sh_done;
    __shared__ unsigned sh_w[8];
    __shared__ float    sh_f[8];
    unsigned target = (unsigned)gridDim.x - 1u;

    for (;;) {
        unsigned s = 0;
        if (threadIdx.x < NCTR)
            s = ld_acq(&g_cnt[threadIdx.x * CTR_STRIDE]);
        s = __reduce_add_sync(FULL, s);                    // per-warp sum
        if ((threadIdx.x & 31) == 0) sh_w[threadIdx.x >> 5] = s;
        __syncthreads();
        if (threadIdx.x == 0)
            sh_done = ((sh_w[0] + sh_w[1]) == target) ? 1 : 0;
        __syncthreads();
        if (sh_done) break;
        __nanosleep(256);
    }

    // all workers' REDs are visible (release->acquire pairs on the counters)
    float acc = 0.0f;
    for (int j = threadIdx.x; j < B; j += blockDim.x) {
        float c  = __ldcg(&g_seg_cnt[j]);
        float sb = __ldcg(&g_seg_bce[j]);
        acc += (c > 0.0f) ? (sb / fmaxf(c, 1.0f)) : 0.0f;
        g_seg_cnt[j] = 0.0f;               // re-zero for next graph replay
        g_seg_bce[j] = 0.0f;
    }
    if (threadIdx.x < NCTR) g_cnt[threadIdx.x * CTR_STRIDE] = 0u;

    #pragma unroll
    for (int o = 16; o; o >>= 1) acc += __shfl_down_sync(FULL, acc, o);
    int lane = threadIdx.x & 31, wid = threadIdx.x >> 5;
    if (lane == 0) sh_f[wid] = acc;
    __syncthreads();
    if (wid == 0) {
        acc = (lane < 8) ? sh_f[lane] : 0.0f;
        #pragma unroll
        for (int o = 16; o; o >>= 1) acc += __shfl_down_sync(FULL, acc, o);
        if (lane == 0) {
            out[0] = acc + __ldcg(&g_sat);
            g_sat = 0.0f;                  // reset for next replay
        }
    }
}

extern "C" void kernel_launch(void* const* d_in, const int* in_sizes, int n_in,
                              void* d_out, int out_size) {
    const float* y_mus_pred = (const float*)d_in[0];
    const float* y_mus      = (const float*)d_in[1];
    const float* y_sat_pred = (const float*)d_in[2];
    const float* y_sat      = (const float*)d_in[3];
    const int*   batch      = (const int*)  d_in[4];
    const int*   mask       = (const int*)  d_in[5];
    int N = in_sizes[0];
    int B = in_sizes[2];
    float L1 = 1.0f / 50.0f;

    int n4 = N >> 2;
    int blocks = (n4 + 255) / 256;
    if (blocks < 1) blocks = 1;

    fused_kernel<<<blocks, 256>>>(y_mus_pred, y_mus, batch, mask,
                                  y_sat_pred, y_sat, (float*)d_out,
                                  n4, N, B, L1);
}